// round 15
// baseline (speedup 1.0000x reference)
#include <cuda_runtime.h>
#include <stdint.h>

#define NTOK 8192
#define DM   2048
#define NE   8
#define FE   1024
#define FS   2048

// ---------------- scratch (device globals; no allocation) ----------------
__device__ float g_wt[NTOK * 2];
__device__ int   g_rowidx[NTOK * 2];
__device__ float g_sg[NTOK];
__device__ int   g_top[NTOK * 2];
__device__ int   g_cnt[NE];
__device__ int   g_list[NE * NTOK];
__device__ float g_acte[(size_t)NE * NTOK * FE];
__device__ float g_acts[(size_t)NTOK * FS];
__device__ float g_eout[(size_t)NE * NTOK * DM];
__device__ float g_ht[(size_t)NTOK * DM];
__device__ float g_wg[(size_t)NE * DM * FE];
__device__ float g_wu[(size_t)NE * DM * FE];
__device__ float g_wd[(size_t)NE * FE * DM];
__device__ float g_wsg2[(size_t)DM * FS];
__device__ float g_wsu[(size_t)DM * FS];
__device__ float g_wsd[(size_t)FS * DM];

// ---------------- helpers ----------------
__device__ __forceinline__ uint32_t f2tf(float x) {
    uint32_t r;
    asm("cvt.rna.tf32.f32 %0, %1;" : "=r"(r) : "f"(x));
    return r;
}
__device__ __forceinline__ float tf32r(float x) { return __uint_as_float(f2tf(x)); }
__device__ __forceinline__ uint32_t au(float x) { return __float_as_uint(x); }
__device__ __forceinline__ uint32_t smem_u32(const void* p) {
    uint32_t a;
    asm("{ .reg .u64 t; cvta.to.shared.u64 t, %1; cvt.u32.u64 %0, t; }" : "=r"(a) : "l"(p));
    return a;
}

__device__ __forceinline__ void mma8(float* c, const uint32_t* a, const uint32_t* b) {
    asm volatile(
        "mma.sync.aligned.m16n8k8.row.col.f32.tf32.tf32.f32 "
        "{%0,%1,%2,%3},{%4,%5,%6,%7},{%8,%9},{%0,%1,%2,%3};"
        : "+f"(c[0]), "+f"(c[1]), "+f"(c[2]), "+f"(c[3])
        : "r"(a[0]), "r"(a[1]), "r"(a[2]), "r"(a[3]), "r"(b[0]), "r"(b[1]));
}

#define CP16(dst, src) \
    asm volatile("cp.async.cg.shared.global [%0], [%1], 16;" :: "r"(dst), "l"(src) : "memory")
#define CP16Z(dst, src, sz) \
    asm volatile("cp.async.cg.shared.global [%0], [%1], 16, %2;" :: "r"(dst), "l"(src), "r"(sz) : "memory")
#define CPCOMMIT() asm volatile("cp.async.commit_group;" ::: "memory")
#define CPWAIT(n)  asm volatile("cp.async.wait_group %0;" :: "n"(n) : "memory")

// ---------------- prep: tf32-round inputs/weights (layout preserved) ----------------
__global__ void round_kernel(const float* __restrict__ h, const float* __restrict__ w_gate,
                             const float* __restrict__ w_up, const float* __restrict__ w_down,
                             const float* __restrict__ ws_gate, const float* __restrict__ ws_up,
                             const float* __restrict__ ws_down) {
    int which = blockIdx.y;
    const float* in; float* out; size_t n;
    switch (which) {
        case 0: in = h;       out = g_ht;   n = (size_t)NTOK * DM;     break;
        case 1: in = w_gate;  out = g_wg;   n = (size_t)NE * DM * FE;  break;
        case 2: in = w_up;    out = g_wu;   n = (size_t)NE * DM * FE;  break;
        case 3: in = w_down;  out = g_wd;   n = (size_t)NE * FE * DM;  break;
        case 4: in = ws_gate; out = g_wsg2; n = (size_t)DM * FS;       break;
        case 5: in = ws_up;   out = g_wsu;  n = (size_t)DM * FS;       break;
        default:in = ws_down; out = g_wsd;  n = (size_t)FS * DM;       break;
    }
    size_t n4 = n >> 2;
    for (size_t i = (size_t)blockIdx.x * blockDim.x + threadIdx.x; i < n4;
         i += (size_t)gridDim.x * blockDim.x) {
        float4 v = reinterpret_cast<const float4*>(in)[i];
        v.x = tf32r(v.x); v.y = tf32r(v.y); v.z = tf32r(v.z); v.w = tf32r(v.w);
        reinterpret_cast<float4*>(out)[i] = v;
    }
}

// ---------------- router ----------------
__global__ void router_kernel(const float* __restrict__ h,
                              const float* __restrict__ gw,
                              const float* __restrict__ wsg) {
    int lane = threadIdx.x & 31;
    int t = blockIdx.x * (blockDim.x >> 5) + (threadIdx.x >> 5);
    if (t >= NTOK) return;
    const float* hr = h + (size_t)t * DM;
    float acc[8];
#pragma unroll
    for (int i = 0; i < 8; i++) acc[i] = 0.f;
    float as_ = 0.f;
    for (int d = lane; d < DM; d += 32) {
        float hv = hr[d];
        const float4* gr = reinterpret_cast<const float4*>(gw + (size_t)d * NE);
        float4 g0 = gr[0], g1 = gr[1];
        acc[0] += hv * g0.x; acc[1] += hv * g0.y; acc[2] += hv * g0.z; acc[3] += hv * g0.w;
        acc[4] += hv * g1.x; acc[5] += hv * g1.y; acc[6] += hv * g1.z; acc[7] += hv * g1.w;
        as_ += hv * wsg[d];
    }
#pragma unroll
    for (int o = 16; o; o >>= 1) {
#pragma unroll
        for (int i = 0; i < 8; i++) acc[i] += __shfl_xor_sync(0xffffffffu, acc[i], o);
        as_ += __shfl_xor_sync(0xffffffffu, as_, o);
    }
    if (lane == 0) {
        int i1 = 0;
#pragma unroll
        for (int e = 1; e < 8; e++) if (acc[e] > acc[i1]) i1 = e;
        int i2 = -1;
#pragma unroll
        for (int e = 0; e < 8; e++) {
            if (e == i1) continue;
            if (i2 < 0 || acc[e] > acc[i2]) i2 = e;
        }
        float e2 = __expf(acc[i2] - acc[i1]);
        float w1 = 1.f / (1.f + e2);
        float w2 = e2 / (1.f + e2);
        g_wt[t * 2] = w1;
        g_wt[t * 2 + 1] = w2;
        g_top[t * 2] = i1;
        g_top[t * 2 + 1] = i2;
        g_sg[t] = 1.f / (1.f + __expf(-as_));
    }
}

__global__ void build_lists_kernel() {
    int e = blockIdx.x;
    int tid = threadIdx.x;
    __shared__ int warp_cnt[8];
    __shared__ int s_base;
    if (tid == 0) s_base = 0;
    __syncthreads();
    for (int base = 0; base < NTOK; base += 256) {
        int t = base + tid;
        int top0 = g_top[t * 2], top1 = g_top[t * 2 + 1];
        int flag = (top0 == e) || (top1 == e);
        unsigned bal = __ballot_sync(0xffffffffu, flag);
        int lane = tid & 31, w = tid >> 5;
        if (lane == 0) warp_cnt[w] = __popc(bal);
        __syncthreads();
        int off = 0;
        for (int i = 0; i < w; i++) off += warp_cnt[i];
        int pos = s_base + off + __popc(bal & ((1u << lane) - 1u));
        if (flag) {
            g_list[e * NTOK + pos] = t;
            int slot = (top0 == e) ? 0 : 1;
            g_rowidx[t * 2 + slot] = e * NTOK + pos;
        }
        __syncthreads();
        if (tid == 0) {
            int tot = 0;
            for (int i = 0; i < 8; i++) tot += warp_cnt[i];
            s_base += tot;
        }
        __syncthreads();
    }
    if (tid == 0) g_cnt[e] = s_base;
}

// =====================================================================
// 512-thread CTAs, BM=256, BK=32, 2-stage. 16 warps = 4 per SMSP.
//  A : [m 0..255][k 0..31], row stride 36 words (==4 mod 32). Frags CF.
//  B : [k 0..31][n], row stride 136 (BN=128) / 264 (BN=256) (==8 mod 32). CF.
// =====================================================================
#define ASTR   36
#define ASZ    (256 * ASTR)          // 9216 words
#define B1STR  136
#define B1SZ   (32 * B1STR)          // 4352 words
#define B2STR  264
#define B2SZ   (32 * B2STR)          // 8448 words
#define G1_STAGE (ASZ + 2 * B1SZ)    // 17920 words (71680 B)
#define G2_STAGE (ASZ + B2SZ)        // 17664 words (70656 B)
#define G1_SMEM (2 * G1_STAGE * 4)   // 143360 B
#define G2_SMEM (2 * G2_STAGE * 4)   // 141312 B

// ---------------- GEMM1 merged: z=0 shared, z>=1 expert; M=256 N=128 BK=32 ----
#define G1_CP(T_, BUF)                                                           \
    {                                                                            \
        const int _k0 = (T_) * 32;                                               \
        const size_t _bo = (size_t)_k0 * ldb;                                    \
        uint32_t _d = smb + (BUF) * (G1_STAGE * 4);                              \
        _Pragma("unroll") for (int p = 0; p < 4; p++)                            \
            CP16Z(_d + adst[p] * 4, Asrc[p] + _k0, asz[p]);                      \
        _Pragma("unroll") for (int j = 0; j < 2; j++) {                          \
            CP16(_d + (ASZ + bdst[j]) * 4, Bsrc1[j] + _bo);                      \
            CP16(_d + (ASZ + B1SZ + bdst[j]) * 4, Bsrc2[j] + _bo);               \
        }                                                                        \
    }

#define G1_COMP(BUF)                                                             \
    {                                                                            \
        const float* SA = sm + (BUF) * G1_STAGE;                                 \
        const float* SB1 = SA + ASZ;                                             \
        const float* SB2 = SB1 + B1SZ;                                           \
        _Pragma("unroll") for (int kt = 0; kt < 4; kt++) {                       \
            const int ks = kt * 8;                                               \
            uint32_t a[4][4], b1[4][2], b2[4][2];                                \
            _Pragma("unroll") for (int im = 0; im < 4; im++) {                   \
                const int m0 = wm_i * 64 + im * 16;                              \
                a[im][0] = au(SA[(m0 + grp) * ASTR + ks + tg]);                  \
                a[im][1] = au(SA[(m0 + 8 + grp) * ASTR + ks + tg]);              \
                a[im][2] = au(SA[(m0 + grp) * ASTR + ks + tg + 4]);              \
                a[im][3] = au(SA[(m0 + 8 + grp) * ASTR + ks + tg + 4]);          \
            }                                                                    \
            _Pragma("unroll") for (int in = 0; in < 4; in++) {                   \
                const int nb = wn_i * 32 + in * 8 + grp;                         \
                b1[in][0] = au(SB1[(ks + tg) * B1STR + nb]);                     \
                b1[in][1] = au(SB1[(ks + tg + 4) * B1STR + nb]);                 \
                b2[in][0] = au(SB2[(ks + tg) * B1STR + nb]);                     \
                b2[in][1] = au(SB2[(ks + tg + 4) * B1STR + nb]);                 \
            }                                                                    \
            _Pragma("unroll") for (int im = 0; im < 4; im++)                     \
                _Pragma("unroll") for (int in = 0; in < 4; in++) {               \
                    mma8(c1[im][in], a[im], b1[in]);                             \
                    mma8(c2[im][in], a[im], b2[in]);                             \
                }                                                                \
        }                                                                        \
    }

__global__ __launch_bounds__(512, 1)
void gemm1_kernel() {
    extern __shared__ float sm[];
    const bool EXPERT = blockIdx.z > 0;
    const int e = EXPERT ? (int)blockIdx.z - 1 : 0;
    if (EXPERT && blockIdx.x >= FE / 128) return;
    const int M = EXPERT ? g_cnt[e] : NTOK;
    const int row0 = blockIdx.y * 256;
    if (row0 >= M) return;
    const int n0 = blockIdx.x * 128;
    const int ldb = EXPERT ? FE : FS;
    const float* B1 = EXPERT ? (g_wg + (size_t)e * DM * FE) : g_wsg2;
    const float* B2 = EXPERT ? (g_wu + (size_t)e * DM * FE) : g_wsu;
    float* C = EXPERT ? (g_acte + (size_t)e * NTOK * FE) : g_acts;
    const int* rl = g_list + e * NTOK;

    const int tid = threadIdx.x, l = tid & 31, w = tid >> 5;
    const uint32_t smb = smem_u32(sm);

    // A: 256 rows x 8 chunks(16B) = 2048; thread -> rows (tid>>3)+64p, chunk tid&7
    const int arow = tid >> 3, akq = tid & 7;
    int adst[4];
    uint32_t asz[4];
    const float* Asrc[4];
#pragma unroll
    for (int p = 0; p < 4; p++) {
        int rloc = arow + 64 * p;
        adst[p] = rloc * ASTR + akq * 4;
        int r = row0 + rloc;
        asz[p] = r < M ? 16u : 0u;
        int s = r < M ? (EXPERT ? rl[r] : r) : 0;
        Asrc[p] = g_ht + (size_t)s * DM + akq * 4;
    }
    // B: 32 k-rows x 32 chunks per matrix = 1024; thread -> k (tid>>5)+16j, chunk tid&31
    const int bk_ = tid >> 5, bnq = tid & 31;
    int bdst[2];
    const float* Bsrc1[2];
    const float* Bsrc2[2];
#pragma unroll
    for (int j = 0; j < 2; j++) {
        int kk = bk_ + 16 * j;
        bdst[j] = kk * B1STR + bnq * 4;
        Bsrc1[j] = B1 + (size_t)kk * ldb + n0 + bnq * 4;
        Bsrc2[j] = B2 + (size_t)kk * ldb + n0 + bnq * 4;
    }

    // 16 warps: 4(m) x 4(n); warp tile 64m x 32n per matrix
    const int wm_i = w >> 2, wn_i = w & 3, grp = l >> 2, tg = l & 3;

    float c1[4][4][4], c2[4][4][4];
#pragma unroll
    for (int i = 0; i < 4; i++)
#pragma unroll
        for (int j = 0; j < 4; j++)
#pragma unroll
            for (int q = 0; q < 4; q++) { c1[i][j][q] = 0.f; c2[i][j][q] = 0.f; }

    const int T = DM / 32;
    G1_CP(0, 0) CPCOMMIT();
    int buf = 0;
    for (int t = 0; t < T; t++) {
        CPWAIT(0);
        __syncthreads();
        if (t + 1 < T) { G1_CP(t + 1, buf ^ 1) CPCOMMIT(); }
        G1_COMP(buf)
        buf ^= 1;
    }

    const int ldc = ldb;
#pragma unroll
    for (int im = 0; im < 4; im++) {
        int r = row0 + wm_i * 64 + im * 16 + grp;
#pragma unroll
        for (int in = 0; in < 4; in++) {
            int cc = n0 + wn_i * 32 + in * 8 + 2 * tg;
            if (r < M) {
                float g0 = c1[im][in][0], u0 = c2[im][in][0];
                float g1 = c1[im][in][1], u1 = c2[im][in][1];
                float2 o;
                o.x = tf32r(g0 * (1.f / (1.f + __expf(-g0))) * u0);
                o.y = tf32r(g1 * (1.f / (1.f + __expf(-g1))) * u1);
                *reinterpret_cast<float2*>(&C[(size_t)r * ldc + cc]) = o;
            }
            if (r + 8 < M) {
                float g0 = c1[im][in][2], u0 = c2[im][in][2];
                float g1 = c1[im][in][3], u1 = c2[im][in][3];
                float2 o;
                o.x = tf32r(g0 * (1.f / (1.f + __expf(-g0))) * u0);
                o.y = tf32r(g1 * (1.f / (1.f + __expf(-g1))) * u1);
                *reinterpret_cast<float2*>(&C[(size_t)(r + 8) * ldc + cc]) = o;
            }
        }
    }
}

// ---------------- GEMM2 merged: z=0 shared->out, z>=1 expert->g_eout ----------
// M=256, N=256, BK=32, 512 thr, warps 4(m) x 4(n), warp tile 64x64.
#define G2_CP(T_, BUF)                                                           \
    {                                                                            \
        const int _k0 = (T_) * 32;                                               \
        const size_t _bo = (size_t)_k0 * DM;                                     \
        uint32_t _d = smb + (BUF) * (G2_STAGE * 4);                              \
        _Pragma("unroll") for (int p = 0; p < 4; p++)                            \
            CP16Z(_d + adst[p] * 4, Asrc[p] + _k0, asz[p]);                      \
        _Pragma("unroll") for (int j = 0; j < 4; j++)                            \
            CP16(_d + (ASZ + bdst[j]) * 4, Bsrc[j] + _bo);                       \
    }

#define G2_COMP(BUF)                                                             \
    {                                                                            \
        const float* SA = sm + (BUF) * G2_STAGE;                                 \
        const float* SB = SA + ASZ;                                              \
        _Pragma("unroll") for (int kt = 0; kt < 4; kt++) {                       \
            const int ks = kt * 8;                                               \
            uint32_t a[4][4], b[8][2];                                           \
            _Pragma("unroll") for (int im = 0; im < 4; im++) {                   \
                const int m0 = wm_i * 64 + im * 16;                              \
                a[im][0] = au(SA[(m0 + grp) * ASTR + ks + tg]);                  \
                a[im][1] = au(SA[(m0 + 8 + grp) * ASTR + ks + tg]);              \
                a[im][2] = au(SA[(m0 + grp) * ASTR + ks + tg + 4]);              \
                a[im][3] = au(SA[(m0 + 8 + grp) * ASTR + ks + tg + 4]);          \
            }                                                                    \
            _Pragma("unroll") for (int in = 0; in < 8; in++) {                   \
                const int nb = wn_i * 64 + in * 8 + grp;                         \
                b[in][0] = au(SB[(ks + tg) * B2STR + nb]);                       \
                b[in][1] = au(SB[(ks + tg + 4) * B2STR + nb]);                   \
            }                                                                    \
            _Pragma("unroll") for (int im = 0; im < 4; im++)                     \
                _Pragma("unroll") for (int in = 0; in < 8; in++)                 \
                    mma8(c[im][in], a[im], b[in]);                               \
        }                                                                        \
    }

__global__ __launch_bounds__(512, 1)
void gemm2_kernel(float* __restrict__ out) {
    extern __shared__ float sm[];
    const bool EXPERT = blockIdx.z > 0;
    const int e = EXPERT ? (int)blockIdx.z - 1 : 0;
    const int M = EXPERT ? g_cnt[e] : NTOK;
    const int row0 = blockIdx.y * 256;
    if (row0 >= M) return;
    const int n0 = blockIdx.x * 256;
    const int K = EXPERT ? FE : FS;
    const float* Aact = EXPERT ? (g_acte + (size_t)e * NTOK * FE) : g_acts;
    const float* B = EXPERT ? (g_wd + (size_t)e * FE * DM) : g_wsd;

    const int tid = threadIdx.x, l = tid & 31, w = tid >> 5;
    const uint32_t smb = smem_u32(sm);

    const int arow = tid >> 3, akq = tid & 7;
    int adst[4];
    uint32_t asz[4];
    const float* Asrc[4];
#pragma unroll
    for (int p = 0; p < 4; p++) {
        int rloc = arow + 64 * p;
        adst[p] = rloc * ASTR + akq * 4;
        int r = row0 + rloc;
        asz[p] = r < M ? 16u : 0u;
        Asrc[p] = Aact + (size_t)(r < M ? r : 0) * K + akq * 4;
    }
    // B: 32 k-rows x 64 chunks = 2048; thread -> k (tid>>6)+8j, chunk tid&63
    const int bk_ = tid >> 6, bnq = tid & 63;
    int bdst[4];
    const float* Bsrc[4];
#pragma unroll
    for (int j = 0; j < 4; j++) {
        int kk = bk_ + 8 * j;
        bdst[j] = kk * B2STR + bnq * 4;
        Bsrc[j] = B + (size_t)kk * DM + n0 + bnq * 4;
    }

    const int wm_i = w >> 2, wn_i = w & 3, grp = l >> 2, tg = l & 3;

    float c[4][8][4];
#pragma unroll
    for (int i = 0; i < 4; i++)
#pragma unroll
        for (int j = 0; j < 8; j++)
#pragma unroll
            for (int q = 0; q < 4; q++) c[i][j][q] = 0.f;

    const int T = K / 32;
    G2_CP(0, 0) CPCOMMIT();
    int buf = 0;
    for (int t = 0; t < T; t++) {
        CPWAIT(0);
        __syncthreads();
        if (t + 1 < T) { G2_CP(t + 1, buf ^ 1) CPCOMMIT(); }
        G2_COMP(buf)
        buf ^= 1;
    }

#pragma unroll
    for (int im = 0; im < 4; im++) {
        int r = row0 + wm_i * 64 + im * 16 + grp;
        float s0 = 0.f, s1 = 0.f;
        if (!EXPERT) {
            if (r < M)     s0 = g_sg[r];
            if (r + 8 < M) s1 = g_sg[r + 8];
        }
#pragma unroll
        for (int in = 0; in < 8; in++) {
            int cc = n0 + wn_i * 64 + in * 8 + 2 * tg;
            if (r < M) {
                if (EXPERT) {
                    float2 o; o.x = c[im][in][0]; o.y = c[im][in][1];
                    *reinterpret_cast<float2*>(
                        &g_eout[((size_t)e * NTOK + r) * DM + cc]) = o;
                } else {
                    float2 o; o.x = s0 * c[im][in][0]; o.y = s0 * c[im][in][1];
                    *reinterpret_cast<float2*>(&out[(size_t)r * DM + cc]) = o;
                }
            }
            if (r + 8 < M) {
                if (EXPERT) {
                    float2 o; o.x = c[im][in][2]; o.y = c[im][in][3];
                    *reinterpret_cast<float2*>(
                        &g_eout[((size_t)e * NTOK + r + 8) * DM + cc]) = o;
                } else {
                    float2 o; o.x = s1 * c[im][in][2]; o.y = s1 * c[im][in][3];
                    *reinterpret_cast<float2*>(&out[(size_t)(r + 8) * DM + cc]) = o;
                }
            }
        }
    }
}

// ---------------- combine: out[t] += w0*eout[idx0] + w1*eout[idx1] ------------
__global__ void combine_kernel(float* __restrict__ out) {
    int t = blockIdx.x;
    int d = threadIdx.x;
    int i0 = g_rowidx[2 * t], i1 = g_rowidx[2 * t + 1];
    float w0 = g_wt[2 * t], w1 = g_wt[2 * t + 1];
    const float4* r0 = reinterpret_cast<const float4*>(g_eout + (size_t)i0 * DM);
    const float4* r1 = reinterpret_cast<const float4*>(g_eout + (size_t)i1 * DM);
    float4* o = reinterpret_cast<float4*>(out + (size_t)t * DM);
#pragma unroll
    for (int j = 0; j < 2; j++) {
        int idx = d + 256 * j;
        float4 a = r0[idx], b = r1[idx], c = o[idx];
        c.x += w0 * a.x + w1 * b.x;
        c.y += w0 * a.y + w1 * b.y;
        c.z += w0 * a.z + w1 * b.z;
        c.w += w0 * a.w + w1 * b.w;
        o[idx] = c;
    }
}

// ---------------- launch ----------------
extern "C" void kernel_launch(void* const* d_in, const int* in_sizes, int n_in,
                              void* d_out, int out_size) {
    const float* h       = (const float*)d_in[0];
    const float* gate_w  = (const float*)d_in[1];
    const float* w_gate  = (const float*)d_in[2];
    const float* w_up    = (const float*)d_in[3];
    const float* w_down  = (const float*)d_in[4];
    const float* ws_gate = (const float*)d_in[5];
    const float* ws_up   = (const float*)d_in[6];
    const float* ws_down = (const float*)d_in[7];
    const float* wsg     = (const float*)d_in[8];
    float* out = (float*)d_out;

    cudaFuncSetAttribute(gemm1_kernel, cudaFuncAttributeMaxDynamicSharedMemorySize, G1_SMEM);
    cudaFuncSetAttribute(gemm2_kernel, cudaFuncAttributeMaxDynamicSharedMemorySize, G2_SMEM);

    round_kernel<<<dim3(512, 7), 256>>>(h, w_gate, w_up, w_down, ws_gate, ws_up, ws_down);
    router_kernel<<<NTOK / 8, 256>>>(h, gate_w, wsg);
    build_lists_kernel<<<NE, 256>>>();

    // merged: z=0 shared (x: FS/128=16), z=1..8 experts (x<FE/128=8 used)
    gemm1_kernel<<<dim3(FS / 128, NTOK / 256, NE + 1), 512, G1_SMEM>>>();
    // merged: z=0 shared, z=1..8 experts (x: DM/256=8)
    gemm2_kernel<<<dim3(DM / 256, NTOK / 256, NE + 1), 512, G2_SMEM>>>(out);
    combine_kernel<<<NTOK, 256>>>(out);
}

// round 17
// speedup vs baseline: 2.8220x; 2.8220x over previous
#include <cuda_runtime.h>
#include <stdint.h>

#define NTOK 8192
#define DM   2048
#define NE   8
#define FE   1024
#define FS   2048

// ---------------- scratch (device globals; no allocation) ----------------
__device__ float g_wt[NTOK * 2];
__device__ int   g_rowidx[NTOK * 2];
__device__ float g_sg[NTOK];
__device__ int   g_top[NTOK * 2];
__device__ int   g_cnt[NE];
__device__ int   g_list[NE * NTOK];
__device__ float g_acte[(size_t)NE * NTOK * FE];
__device__ float g_acts[(size_t)NTOK * FS];
__device__ float g_eout[(size_t)NE * NTOK * DM];
__device__ float g_ht[(size_t)NTOK * DM];
__device__ float g_wg[(size_t)NE * DM * FE];
__device__ float g_wu[(size_t)NE * DM * FE];
__device__ float g_wd[(size_t)NE * FE * DM];
__device__ float g_wsg2[(size_t)DM * FS];
__device__ float g_wsu[(size_t)DM * FS];
__device__ float g_wsd[(size_t)FS * DM];

// ---------------- helpers ----------------
__device__ __forceinline__ uint32_t f2tf(float x) {
    uint32_t r;
    asm("cvt.rna.tf32.f32 %0, %1;" : "=r"(r) : "f"(x));
    return r;
}
__device__ __forceinline__ float tf32r(float x) { return __uint_as_float(f2tf(x)); }
__device__ __forceinline__ uint32_t au(float x) { return __float_as_uint(x); }
__device__ __forceinline__ uint32_t smem_u32(const void* p) {
    uint32_t a;
    asm("{ .reg .u64 t; cvta.to.shared.u64 t, %1; cvt.u32.u64 %0, t; }" : "=r"(a) : "l"(p));
    return a;
}

__device__ __forceinline__ void mma8(float* c, const uint32_t* a, const uint32_t* b) {
    asm volatile(
        "mma.sync.aligned.m16n8k8.row.col.f32.tf32.tf32.f32 "
        "{%0,%1,%2,%3},{%4,%5,%6,%7},{%8,%9},{%0,%1,%2,%3};"
        : "+f"(c[0]), "+f"(c[1]), "+f"(c[2]), "+f"(c[3])
        : "r"(a[0]), "r"(a[1]), "r"(a[2]), "r"(a[3]), "r"(b[0]), "r"(b[1]));
}

#define CP16(dst, src) \
    asm volatile("cp.async.cg.shared.global [%0], [%1], 16;" :: "r"(dst), "l"(src) : "memory")
#define CP16Z(dst, src, sz) \
    asm volatile("cp.async.cg.shared.global [%0], [%1], 16, %2;" :: "r"(dst), "l"(src), "r"(sz) : "memory")
#define CPCOMMIT() asm volatile("cp.async.commit_group;" ::: "memory")
#define CPWAIT(n)  asm volatile("cp.async.wait_group %0;" :: "n"(n) : "memory")

// ---------------- prep: tf32-round inputs/weights (layout preserved) ----------------
__global__ void round_kernel(const float* __restrict__ h, const float* __restrict__ w_gate,
                             const float* __restrict__ w_up, const float* __restrict__ w_down,
                             const float* __restrict__ ws_gate, const float* __restrict__ ws_up,
                             const float* __restrict__ ws_down) {
    int which = blockIdx.y;
    const float* in; float* out; size_t n;
    switch (which) {
        case 0: in = h;       out = g_ht;   n = (size_t)NTOK * DM;     break;
        case 1: in = w_gate;  out = g_wg;   n = (size_t)NE * DM * FE;  break;
        case 2: in = w_up;    out = g_wu;   n = (size_t)NE * DM * FE;  break;
        case 3: in = w_down;  out = g_wd;   n = (size_t)NE * FE * DM;  break;
        case 4: in = ws_gate; out = g_wsg2; n = (size_t)DM * FS;       break;
        case 5: in = ws_up;   out = g_wsu;  n = (size_t)DM * FS;       break;
        default:in = ws_down; out = g_wsd;  n = (size_t)FS * DM;       break;
    }
    size_t n4 = n >> 2;
    for (size_t i = (size_t)blockIdx.x * blockDim.x + threadIdx.x; i < n4;
         i += (size_t)gridDim.x * blockDim.x) {
        float4 v = reinterpret_cast<const float4*>(in)[i];
        v.x = tf32r(v.x); v.y = tf32r(v.y); v.z = tf32r(v.z); v.w = tf32r(v.w);
        reinterpret_cast<float4*>(out)[i] = v;
    }
}

// ---------------- router ----------------
__global__ void router_kernel(const float* __restrict__ h,
                              const float* __restrict__ gw,
                              const float* __restrict__ wsg) {
    int lane = threadIdx.x & 31;
    int t = blockIdx.x * (blockDim.x >> 5) + (threadIdx.x >> 5);
    if (t >= NTOK) return;
    const float* hr = h + (size_t)t * DM;
    float acc[8];
#pragma unroll
    for (int i = 0; i < 8; i++) acc[i] = 0.f;
    float as_ = 0.f;
    for (int d = lane; d < DM; d += 32) {
        float hv = hr[d];
        const float4* gr = reinterpret_cast<const float4*>(gw + (size_t)d * NE);
        float4 g0 = gr[0], g1 = gr[1];
        acc[0] += hv * g0.x; acc[1] += hv * g0.y; acc[2] += hv * g0.z; acc[3] += hv * g0.w;
        acc[4] += hv * g1.x; acc[5] += hv * g1.y; acc[6] += hv * g1.z; acc[7] += hv * g1.w;
        as_ += hv * wsg[d];
    }
#pragma unroll
    for (int o = 16; o; o >>= 1) {
#pragma unroll
        for (int i = 0; i < 8; i++) acc[i] += __shfl_xor_sync(0xffffffffu, acc[i], o);
        as_ += __shfl_xor_sync(0xffffffffu, as_, o);
    }
    if (lane == 0) {
        int i1 = 0;
#pragma unroll
        for (int e = 1; e < 8; e++) if (acc[e] > acc[i1]) i1 = e;
        int i2 = -1;
#pragma unroll
        for (int e = 0; e < 8; e++) {
            if (e == i1) continue;
            if (i2 < 0 || acc[e] > acc[i2]) i2 = e;
        }
        float e2 = __expf(acc[i2] - acc[i1]);
        float w1 = 1.f / (1.f + e2);
        float w2 = e2 / (1.f + e2);
        g_wt[t * 2] = w1;
        g_wt[t * 2 + 1] = w2;
        g_top[t * 2] = i1;
        g_top[t * 2 + 1] = i2;
        g_sg[t] = 1.f / (1.f + __expf(-as_));
    }
}

// 1024-thread deterministic list build: 8 serial chunks of 1024 tokens.
__global__ void build_lists_kernel() {
    int e = blockIdx.x;
    int tid = threadIdx.x;
    __shared__ int warp_cnt[32];
    __shared__ int s_base;
    if (tid == 0) s_base = 0;
    __syncthreads();
    for (int base = 0; base < NTOK; base += 1024) {
        int t = base + tid;
        int top0 = g_top[t * 2], top1 = g_top[t * 2 + 1];
        int flag = (top0 == e) || (top1 == e);
        unsigned bal = __ballot_sync(0xffffffffu, flag);
        int lane = tid & 31, w = tid >> 5;
        if (lane == 0) warp_cnt[w] = __popc(bal);
        __syncthreads();
        int off = 0;
        for (int i = 0; i < w; i++) off += warp_cnt[i];
        int pos = s_base + off + __popc(bal & ((1u << lane) - 1u));
        if (flag) {
            g_list[e * NTOK + pos] = t;
            int slot = (top0 == e) ? 0 : 1;
            g_rowidx[t * 2 + slot] = e * NTOK + pos;
        }
        __syncthreads();
        if (tid == 0) {
            int tot = 0;
            for (int i = 0; i < 32; i++) tot += warp_cnt[i];
            s_base += tot;
        }
        __syncthreads();
    }
    if (tid == 0) g_cnt[e] = s_base;
}

// =====================================================================
// SMEM layouts (floats), BK = 64, 2-stage (R10/R14-proven):
//  A : [m 0..127][k 0..63], row stride 68 words. Fragment reads conflict-free.
//  B : [k 0..63][n], row stride 136 (BN=128) / 264 (BN=256), ==8 mod 32. CF.
// =====================================================================
#define ASTR   68
#define ASZ    (128 * ASTR)
#define B1STR  136
#define B1SZ   (64 * B1STR)
#define B2STR  264
#define B2SZ   (64 * B2STR)
#define G1_STAGE (ASZ + 2 * B1SZ)
#define G2_STAGE (ASZ + B2SZ)
#define G1_SMEM (2 * G1_STAGE * 4)
#define G2_SMEM (2 * G2_STAGE * 4)

// ---------------- GEMM1 merged: z=0 shared, z>=1 expert; M=128 N=128 BK=64 ----
#define G1_CP(T_, BUF)                                                           \
    {                                                                            \
        const int _k0 = (T_) * 64;                                               \
        const size_t _bo = (size_t)_k0 * ldb;                                    \
        uint32_t _d = smb + (BUF) * (G1_STAGE * 4);                              \
        _Pragma("unroll") for (int p = 0; p < 8; p++)                            \
            CP16Z(_d + adst[p] * 4, Asrc[p] + _k0, asz[p]);                      \
        _Pragma("unroll") for (int j = 0; j < 8; j++) {                          \
            CP16(_d + (ASZ + bdst[j]) * 4, Bsrc1[j] + _bo);                      \
            CP16(_d + (ASZ + B1SZ + bdst[j]) * 4, Bsrc2[j] + _bo);               \
        }                                                                        \
    }

#define G1_COMP(BUF)                                                             \
    {                                                                            \
        const float* SA = sm + (BUF) * G1_STAGE;                                 \
        const float* SB1 = SA + ASZ;                                             \
        const float* SB2 = SB1 + B1SZ;                                           \
        _Pragma("unroll") for (int kt = 0; kt < 8; kt++) {                       \
            const int ks = kt * 8;                                               \
            uint32_t a[4][4], b1[4][2], b2[4][2];                                \
            _Pragma("unroll") for (int im = 0; im < 4; im++) {                   \
                const int m0 = wm_i * 64 + im * 16;                              \
                a[im][0] = au(SA[(m0 + grp) * ASTR + ks + tg]);                  \
                a[im][1] = au(SA[(m0 + 8 + grp) * ASTR + ks + tg]);              \
                a[im][2] = au(SA[(m0 + grp) * ASTR + ks + tg + 4]);              \
                a[im][3] = au(SA[(m0 + 8 + grp) * ASTR + ks + tg + 4]);          \
            }                                                                    \
            _Pragma("unroll") for (int in = 0; in < 4; in++) {                   \
                const int nb = wn_i * 32 + in * 8 + grp;                         \
                b1[in][0] = au(SB1[(ks + tg) * B1STR + nb]);                     \
                b1[in][1] = au(SB1[(ks + tg + 4) * B1STR + nb]);                 \
                b2[in][0] = au(SB2[(ks + tg) * B1STR + nb]);                     \
                b2[in][1] = au(SB2[(ks + tg + 4) * B1STR + nb]);                 \
            }                                                                    \
            _Pragma("unroll") for (int im = 0; im < 4; im++)                     \
                _Pragma("unroll") for (int in = 0; in < 4; in++) {               \
                    mma8(c1[im][in], a[im], b1[in]);                             \
                    mma8(c2[im][in], a[im], b2[in]);                             \
                }                                                                \
        }                                                                        \
    }

__global__ __launch_bounds__(256, 1)
void gemm1_kernel() {
    extern __shared__ float sm[];
    const bool EXPERT = blockIdx.z > 0;
    const int e = EXPERT ? (int)blockIdx.z - 1 : 0;
    if (EXPERT && blockIdx.x >= FE / 128) return;
    const int M = EXPERT ? g_cnt[e] : NTOK;
    const int row0 = blockIdx.y * 128;
    if (row0 >= M) return;
    const int n0 = blockIdx.x * 128;
    const int ldb = EXPERT ? FE : FS;
    const float* B1 = EXPERT ? (g_wg + (size_t)e * DM * FE) : g_wsg2;
    const float* B2 = EXPERT ? (g_wu + (size_t)e * DM * FE) : g_wsu;
    float* C = EXPERT ? (g_acte + (size_t)e * NTOK * FE) : g_acts;
    const int* rl = g_list + e * NTOK;

    const int tid = threadIdx.x, l = tid & 31, w = tid >> 5;
    const uint32_t smb = smem_u32(sm);

    const int arow = tid >> 4, akq = tid & 15;
    int adst[8];
    uint32_t asz[8];
    const float* Asrc[8];
#pragma unroll
    for (int p = 0; p < 8; p++) {
        int rloc = arow + 16 * p;
        adst[p] = rloc * ASTR + akq * 4;
        int r = row0 + rloc;
        asz[p] = r < M ? 16u : 0u;
        int s = r < M ? (EXPERT ? rl[r] : r) : 0;
        Asrc[p] = g_ht + (size_t)s * DM + akq * 4;
    }
    const int bk_ = tid >> 5, bnq = tid & 31;
    int bdst[8];
    const float* Bsrc1[8];
    const float* Bsrc2[8];
#pragma unroll
    for (int j = 0; j < 8; j++) {
        int kk = bk_ + 8 * j;
        bdst[j] = kk * B1STR + bnq * 4;
        Bsrc1[j] = B1 + (size_t)kk * ldb + n0 + bnq * 4;
        Bsrc2[j] = B2 + (size_t)kk * ldb + n0 + bnq * 4;
    }

    const int wm_i = w >> 2, wn_i = w & 3, grp = l >> 2, tg = l & 3;

    float c1[4][4][4], c2[4][4][4];
#pragma unroll
    for (int i = 0; i < 4; i++)
#pragma unroll
        for (int j = 0; j < 4; j++)
#pragma unroll
            for (int q = 0; q < 4; q++) { c1[i][j][q] = 0.f; c2[i][j][q] = 0.f; }

    const int T = DM / 64;
    G1_CP(0, 0) CPCOMMIT();
    int buf = 0;
    for (int t = 0; t < T; t++) {
        CPWAIT(0);
        __syncthreads();
        if (t + 1 < T) { G1_CP(t + 1, buf ^ 1) CPCOMMIT(); }
        G1_COMP(buf)
        buf ^= 1;
    }

    const int ldc = ldb;
#pragma unroll
    for (int im = 0; im < 4; im++) {
        int r = row0 + wm_i * 64 + im * 16 + grp;
#pragma unroll
        for (int in = 0; in < 4; in++) {
            int cc = n0 + wn_i * 32 + in * 8 + 2 * tg;
            if (r < M) {
                float g0 = c1[im][in][0], u0 = c2[im][in][0];
                float g1 = c1[im][in][1], u1 = c2[im][in][1];
                float2 o;
                o.x = tf32r(g0 * (1.f / (1.f + __expf(-g0))) * u0);
                o.y = tf32r(g1 * (1.f / (1.f + __expf(-g1))) * u1);
                *reinterpret_cast<float2*>(&C[(size_t)r * ldc + cc]) = o;
            }
            if (r + 8 < M) {
                float g0 = c1[im][in][2], u0 = c2[im][in][2];
                float g1 = c1[im][in][3], u1 = c2[im][in][3];
                float2 o;
                o.x = tf32r(g0 * (1.f / (1.f + __expf(-g0))) * u0);
                o.y = tf32r(g1 * (1.f / (1.f + __expf(-g1))) * u1);
                *reinterpret_cast<float2*>(&C[(size_t)(r + 8) * ldc + cc]) = o;
            }
        }
    }
}

// ---------------- GEMM2 merged: z=0 shared->out, z>=1 expert->g_eout ----------
#define G2_CP(T_, BUF)                                                           \
    {                                                                            \
        const int _k0 = (T_) * 64;                                               \
        const size_t _bo = (size_t)_k0 * DM;                                     \
        uint32_t _d = smb + (BUF) * (G2_STAGE * 4);                              \
        _Pragma("unroll") for (int p = 0; p < 8; p++)                            \
            CP16Z(_d + adst[p] * 4, Asrc[p] + _k0, asz[p]);                      \
        _Pragma("unroll") for (int j = 0; j < 16; j++)                           \
            CP16(_d + (ASZ + bdst[j]) * 4, Bsrc[j] + _bo);                       \
    }

#define G2_COMP(BUF)                                                             \
    {                                                                            \
        const float* SA = sm + (BUF) * G2_STAGE;                                 \
        const float* SB = SA + ASZ;                                              \
        _Pragma("unroll") for (int kt = 0; kt < 8; kt++) {                       \
            const int ks = kt * 8;                                               \
            uint32_t a[4][4], b[8][2];                                           \
            _Pragma("unroll") for (int im = 0; im < 4; im++) {                   \
                const int m0 = wm_i * 64 + im * 16;                              \
                a[im][0] = au(SA[(m0 + grp) * ASTR + ks + tg]);                  \
                a[im][1] = au(SA[(m0 + 8 + grp) * ASTR + ks + tg]);              \
                a[im][2] = au(SA[(m0 + grp) * ASTR + ks + tg + 4]);              \
                a[im][3] = au(SA[(m0 + 8 + grp) * ASTR + ks + tg + 4]);          \
            }                                                                    \
            _Pragma("unroll") for (int in = 0; in < 8; in++) {                   \
                const int nb = wn_i * 64 + in * 8 + grp;                         \
                b[in][0] = au(SB[(ks + tg) * B2STR + nb]);                       \
                b[in][1] = au(SB[(ks + tg + 4) * B2STR + nb]);                   \
            }                                                                    \
            _Pragma("unroll") for (int im = 0; im < 4; im++)                     \
                _Pragma("unroll") for (int in = 0; in < 8; in++)                 \
                    mma8(c[im][in], a[im], b[in]);                               \
        }                                                                        \
    }

__global__ __launch_bounds__(256, 1)
void gemm2_kernel(float* __restrict__ out) {
    extern __shared__ float sm[];
    const bool EXPERT = blockIdx.z > 0;
    const int e = EXPERT ? (int)blockIdx.z - 1 : 0;
    const int M = EXPERT ? g_cnt[e] : NTOK;
    const int row0 = blockIdx.y * 128;
    if (row0 >= M) return;
    const int n0 = blockIdx.x * 256;
    const int K = EXPERT ? FE : FS;
    const float* Aact = EXPERT ? (g_acte + (size_t)e * NTOK * FE) : g_acts;
    const float* B = EXPERT ? (g_wd + (size_t)e * FE * DM) : g_wsd;

    const int tid = threadIdx.x, l = tid & 31, w = tid >> 5;
    const uint32_t smb = smem_u32(sm);

    const int arow = tid >> 4, akq = tid & 15;
    int adst[8];
    uint32_t asz[8];
    const float* Asrc[8];
#pragma unroll
    for (int p = 0; p < 8; p++) {
        int rloc = arow + 16 * p;
        adst[p] = rloc * ASTR + akq * 4;
        int r = row0 + rloc;
        asz[p] = r < M ? 16u : 0u;
        Asrc[p] = Aact + (size_t)(r < M ? r : 0) * K + akq * 4;
    }
    const int bk_ = tid >> 6, bnq = tid & 63;
    int bdst[16];
    const float* Bsrc[16];
#pragma unroll
    for (int j = 0; j < 16; j++) {
        int kk = bk_ + 4 * j;
        bdst[j] = kk * B2STR + bnq * 4;
        Bsrc[j] = B + (size_t)kk * DM + n0 + bnq * 4;
    }

    const int wm_i = w >> 2, wn_i = w & 3, grp = l >> 2, tg = l & 3;

    float c[4][8][4];
#pragma unroll
    for (int i = 0; i < 4; i++)
#pragma unroll
        for (int j = 0; j < 8; j++)
#pragma unroll
            for (int q = 0; q < 4; q++) c[i][j][q] = 0.f;

    const int T = K / 64;
    G2_CP(0, 0) CPCOMMIT();
    int buf = 0;
    for (int t = 0; t < T; t++) {
        CPWAIT(0);
        __syncthreads();
        if (t + 1 < T) { G2_CP(t + 1, buf ^ 1) CPCOMMIT(); }
        G2_COMP(buf)
        buf ^= 1;
    }

#pragma unroll
    for (int im = 0; im < 4; im++) {
        int r = row0 + wm_i * 64 + im * 16 + grp;
        float s0 = 0.f, s1 = 0.f;
        if (!EXPERT) {
            if (r < M)     s0 = g_sg[r];
            if (r + 8 < M) s1 = g_sg[r + 8];
        }
#pragma unroll
        for (int in = 0; in < 8; in++) {
            int cc = n0 + wn_i * 64 + in * 8 + 2 * tg;
            if (r < M) {
                if (EXPERT) {
                    float2 o; o.x = c[im][in][0]; o.y = c[im][in][1];
                    *reinterpret_cast<float2*>(
                        &g_eout[((size_t)e * NTOK + r) * DM + cc]) = o;
                } else {
                    float2 o; o.x = s0 * c[im][in][0]; o.y = s0 * c[im][in][1];
                    *reinterpret_cast<float2*>(&out[(size_t)r * DM + cc]) = o;
                }
            }
            if (r + 8 < M) {
                if (EXPERT) {
                    float2 o; o.x = c[im][in][2]; o.y = c[im][in][3];
                    *reinterpret_cast<float2*>(
                        &g_eout[((size_t)e * NTOK + r + 8) * DM + cc]) = o;
                } else {
                    float2 o; o.x = s1 * c[im][in][2]; o.y = s1 * c[im][in][3];
                    *reinterpret_cast<float2*>(&out[(size_t)(r + 8) * DM + cc]) = o;
                }
            }
        }
    }
}

// ---------------- combine: out[t] += w0*eout[idx0] + w1*eout[idx1] ------------
__global__ void combine_kernel(float* __restrict__ out) {
    int t = blockIdx.x;
    int d = threadIdx.x;
    int i0 = g_rowidx[2 * t], i1 = g_rowidx[2 * t + 1];
    float w0 = g_wt[2 * t], w1 = g_wt[2 * t + 1];
    const float4* r0 = reinterpret_cast<const float4*>(g_eout + (size_t)i0 * DM);
    const float4* r1 = reinterpret_cast<const float4*>(g_eout + (size_t)i1 * DM);
    float4* o = reinterpret_cast<float4*>(out + (size_t)t * DM);
    float4 a = r0[d], b = r1[d], c = o[d];
    c.x += w0 * a.x + w1 * b.x;
    c.y += w0 * a.y + w1 * b.y;
    c.z += w0 * a.z + w1 * b.z;
    c.w += w0 * a.w + w1 * b.w;
    o[d] = c;
}

// ---------------- launch ----------------
extern "C" void kernel_launch(void* const* d_in, const int* in_sizes, int n_in,
                              void* d_out, int out_size) {
    const float* h       = (const float*)d_in[0];
    const float* gate_w  = (const float*)d_in[1];
    const float* w_gate  = (const float*)d_in[2];
    const float* w_up    = (const float*)d_in[3];
    const float* w_down  = (const float*)d_in[4];
    const float* ws_gate = (const float*)d_in[5];
    const float* ws_up   = (const float*)d_in[6];
    const float* ws_down = (const float*)d_in[7];
    const float* wsg     = (const float*)d_in[8];
    float* out = (float*)d_out;

    cudaFuncSetAttribute(gemm1_kernel, cudaFuncAttributeMaxDynamicSharedMemorySize, G1_SMEM);
    cudaFuncSetAttribute(gemm2_kernel, cudaFuncAttributeMaxDynamicSharedMemorySize, G2_SMEM);

    round_kernel<<<dim3(1024, 7), 256>>>(h, w_gate, w_up, w_down, ws_gate, ws_up, ws_down);
    router_kernel<<<NTOK / 8, 256>>>(h, gate_w, wsg);
    build_lists_kernel<<<NE, 1024>>>();

    // merged: z=0 shared (x: FS/128=16), z=1..8 experts (x<FE/128=8 used)
    gemm1_kernel<<<dim3(FS / 128, NTOK / 128, NE + 1), 256, G1_SMEM>>>();
    // merged: z=0 shared, z=1..8 experts (x: DM/256=8)
    gemm2_kernel<<<dim3(DM / 256, NTOK / 128, NE + 1), 256, G2_SMEM>>>(out);
    combine_kernel<<<NTOK, 512>>>(out);
}